// round 12
// baseline (speedup 1.0000x reference)
#include <cuda_runtime.h>
#include <cuda_fp16.h>
#include <math.h>

// Problem constants (fixed by setup_inputs)
#define B_    2
#define Q_    12240
#define E_    256
#define VLEN_ 12240
#define BQ_   (B_ * Q_)      // 24480
#define BV_   (B_ * VLEN_)   // 24480
#define NELEM ((size_t)BQ_ * E_)   // 6266880

// Scratch (static __device__ — no allocation)
__device__ __half2 g_vproj_h[(size_t)BV_ * 128];   // (B, Vlen, 128 half2)
__device__ int4    g_sinfo[(size_t)BQ_ * 128];     // per-sample {base, dxdy, wx, wy}
__device__ float   g_attnw[(size_t)BQ_ * 128];     // (bq, h,l,k)
// pre-split operands (v = hi + lo, both fp16)
__device__ __half  g_val_h[NELEM], g_val_l[NELEM];
__device__ __half  g_qry_h[NELEM], g_qry_l[NELEM];
__device__ __half  g_acc_h[NELEM], g_acc_l[NELEM];
// weights packed [k2][n] as half2 of (k even, k odd)
__device__ __half2 g_wv_h[128 * 256], g_wv_l[128 * 256];
__device__ __half2 g_wo_h[128 * 256], g_wo_l[128 * 256];
__device__ __half2 g_wa_h[128 * 128], g_wa_l[128 * 128];
__device__ __half2 g_wu_h[128 * 256], g_wu_l[128 * 256];

// ---------------------------------------------------------------------------
// Prepass: split fp32 -> (hi, lo) fp16 arrays. blockIdx.y: 0 = value, 1 = queries.
// ---------------------------------------------------------------------------
__global__ __launch_bounds__(256)
void split_inputs(const float* __restrict__ v, const float* __restrict__ q,
                  __half* __restrict__ vh, __half* __restrict__ vl,
                  __half* __restrict__ qh, __half* __restrict__ ql) {
    size_t i = ((size_t)blockIdx.x * 256 + threadIdx.x) * 8;
    const float* s = blockIdx.y ? q : v;
    __half* H = blockIdx.y ? qh : vh;
    __half* L = blockIdx.y ? ql : vl;
    float4 a = *(const float4*)(s + i);
    float4 b = *(const float4*)(s + i + 4);
    float f[8] = {a.x, a.y, a.z, a.w, b.x, b.y, b.z, b.w};
    __half hs[8], ls[8];
#pragma unroll
    for (int j = 0; j < 8; j++) {
        hs[j] = __float2half_rn(f[j]);
        ls[j] = __float2half_rn(f[j] - __half2float(hs[j]));
    }
    *(uint4*)(H + i) = *(uint4*)hs;
    *(uint4*)(L + i) = *(uint4*)ls;
}

// ---------------------------------------------------------------------------
// Prepass: pack weights K x N -> [k2][n] half2 (k-pair) hi/lo.
// blockIdx.y: 0 = Wv, 1 = Woff, 2 = Wattn, 3 = Wout.
// ---------------------------------------------------------------------------
__global__ __launch_bounds__(256)
void pack_weights(const float* __restrict__ Wv, const float* __restrict__ Wo,
                  const float* __restrict__ Wa, const float* __restrict__ Wu,
                  __half2* vh, __half2* vl, __half2* oh, __half2* ol,
                  __half2* ah, __half2* al, __half2* uh, __half2* ul) {
    const int y = blockIdx.y;
    const float* S; __half2 *H, *L; int N;
    if      (y == 0) { S = Wv; H = vh; L = vl; N = 256; }
    else if (y == 1) { S = Wo; H = oh; L = ol; N = 256; }
    else if (y == 2) { S = Wa; H = ah; L = al; N = 128; }
    else             { S = Wu; H = uh; L = ul; N = 256; }
    int idx = blockIdx.x * 256 + threadIdx.x;
    if (idx >= 128 * N) return;
    int k2 = idx / N, n = idx - k2 * N;
    float a = S[(size_t)(2 * k2) * N + n];
    float b = S[(size_t)(2 * k2 + 1) * N + n];
    __half ha = __float2half_rn(a), hb = __float2half_rn(b);
    H[idx] = __halves2half2(ha, hb);
    L[idx] = __halves2half2(__float2half_rn(a - __half2float(ha)),
                            __float2half_rn(b - __half2float(hb)));
}

// ---------------------------------------------------------------------------
// 3xFP16 tensor-core GEMM on pre-split operands. Double-buffered smem,
// one sync per k-iter, ldmatrix.x4 A-fragment loads. K = 256 fixed.
// EPI 0: A=acc(hi/lo), B=Wout pack -> fp32 out (grid.x=2)
// EPI 5: grid.x=5: bx 0-1 value*Wv -> fp16 vproj; bx 2-3 queries*Woff -> sinfo;
//        bx 4 queries*Wattn -> attnw (softmax)
// ---------------------------------------------------------------------------
__device__ __forceinline__ void mma_f16(float* c, const unsigned* a, const unsigned* b) {
    asm volatile(
        "mma.sync.aligned.m16n8k16.row.col.f32.f16.f16.f32 "
        "{%0,%1,%2,%3}, {%4,%5,%6,%7}, {%8,%9}, {%0,%1,%2,%3};\n"
        : "+f"(c[0]), "+f"(c[1]), "+f"(c[2]), "+f"(c[3])
        : "r"(a[0]), "r"(a[1]), "r"(a[2]), "r"(a[3]), "r"(b[0]), "r"(b[1]));
}

__device__ __forceinline__ void ldsm_x4(unsigned* r, unsigned saddr) {
    asm volatile("ldmatrix.sync.aligned.m8n8.x4.shared.b16 {%0,%1,%2,%3}, [%4];"
                 : "=r"(r[0]), "=r"(r[1]), "=r"(r[2]), "=r"(r[3]) : "r"(saddr));
}

#define GBM 128
#define GBK 32
#define A_LDH 20                       // half2 ld for A (16 + 4 pad)
#define B_LDH 136                      // half2 ld for B (128 + 8 pad)
#define AS_SZ (GBM * A_LDH)            // 2560 half2
#define BS_SZ (16 * B_LDH)             // 2176 half2
#define STG_H2 (2 * AS_SZ + 2 * BS_SZ) // 9472 half2 = 37888 B
#define STG_B  (STG_H2 * 4)
#define SMEM_TOT (2 * STG_B)           // 75776 B

template<int EPI>
__global__ __launch_bounds__(256, 2)
void gemm_3xfp16(const __half* __restrict__ Ah, const __half* __restrict__ Al,
                 const __half* __restrict__ A2h, const __half* __restrict__ A2l,
                 const __half2* __restrict__ B0h, const __half2* __restrict__ B0l,
                 const __half2* __restrict__ B1h, const __half2* __restrict__ B1l,
                 const __half2* __restrict__ B2h, const __half2* __restrict__ B2l,
                 void* __restrict__ C0, void* __restrict__ C1, void* __restrict__ C2,
                 int M,
                 const float* __restrict__ ref, const float* __restrict__ boff,
                 const float* __restrict__ battn) {
    extern __shared__ __half2 dsm[];
    const unsigned sbase = (unsigned)__cvta_generic_to_shared(dsm);

    const int tid  = threadIdx.x;
    const int warp = tid >> 5;
    const int lane = tid & 31;
    const int grp  = lane >> 2;
    const int tg   = lane & 3;
    const int m_off = (warp >> 2) * 64;
    const int n_off = (warp & 3) * 32;
    const int bm = blockIdx.y * GBM;
    const int bx = blockIdx.x;

    // operand routing
    const __half *pAh, *pAl; const __half2 *pBh, *pBl; int Nb, bn;
    if (EPI == 0) { pAh = Ah;  pAl = Al;  pBh = B0h; pBl = B0l; Nb = 256; bn = bx * 128; }
    else {
        if (bx < 2)      { pAh = Ah;  pAl = Al;  pBh = B0h; pBl = B0l; Nb = 256; bn = bx * 128; }
        else if (bx < 4) { pAh = A2h; pAl = A2l; pBh = B1h; pBl = B1l; Nb = 256; bn = (bx - 2) * 128; }
        else             { pAh = A2h; pAl = A2l; pBh = B2h; pBl = B2l; Nb = 128; bn = 0; }
    }

    float cc[4][4][4];
#pragma unroll
    for (int i = 0; i < 4; i++)
#pragma unroll
        for (int j = 0; j < 4; j++)
#pragma unroll
            for (int r = 0; r < 4; r++) cc[i][j][r] = 0.f;

    // staging thread maps
    const int ar  = tid >> 1;               // A row 0..127
    const int ahs = tid & 1;                // A k-half (16 halves each)
    const bool avalid = (bm + ar) < M;
    const int aoff = ar * A_LDH + ahs * 8;  // smem half2 offset
    const size_t agbase = (size_t)(bm + ar) * 256 + ahs * 16;   // halves

    const int bk2l = tid >> 4;              // B k2 row 0..15
    const int bn8  = (tid & 15) * 8;        // B half2 col
    const int boff2 = bk2l * B_LDH + bn8;
    const size_t bgbase = (size_t)bk2l * Nb + bn + bn8;         // half2

    // ldmatrix lane offset (bytes)
    const int lds_lane = ((lane & 15) * A_LDH + 4 * (lane >> 4)) * 4;

    uint4 pah[2], pal[2], pbh[2], pbl[2];
    const uint4 zero4 = make_uint4(0, 0, 0, 0);

    // initial gmem loads (k0 = 0)
    pah[0] = avalid ? *(const uint4*)(pAh + agbase)     : zero4;
    pah[1] = avalid ? *(const uint4*)(pAh + agbase + 8) : zero4;
    pal[0] = avalid ? *(const uint4*)(pAl + agbase)     : zero4;
    pal[1] = avalid ? *(const uint4*)(pAl + agbase + 8) : zero4;
    pbh[0] = *(const uint4*)((const __half2*)pBh + bgbase);
    pbh[1] = *(const uint4*)((const __half2*)pBh + bgbase + 4);
    pbl[0] = *(const uint4*)((const __half2*)pBl + bgbase);
    pbl[1] = *(const uint4*)((const __half2*)pBl + bgbase + 4);

    // store stage 0
    {
        __half2* As_hi = dsm;
        __half2* As_lo = As_hi + AS_SZ;
        __half2* Bs_hi = As_lo + AS_SZ;
        __half2* Bs_lo = Bs_hi + BS_SZ;
        *(uint4*)&As_hi[aoff] = pah[0]; *(uint4*)&As_hi[aoff + 4] = pah[1];
        *(uint4*)&As_lo[aoff] = pal[0]; *(uint4*)&As_lo[aoff + 4] = pal[1];
        *(uint4*)&Bs_hi[boff2] = pbh[0]; *(uint4*)&Bs_hi[boff2 + 4] = pbh[1];
        *(uint4*)&Bs_lo[boff2] = pbl[0]; *(uint4*)&Bs_lo[boff2 + 4] = pbl[1];
    }
    __syncthreads();

    int buf = 0;
#pragma unroll 1
    for (int k0 = 0; k0 < 256; k0 += GBK) {
        const bool notlast = (k0 + GBK < 256);
        // ---- prefetch next tile ----
        if (notlast) {
            const size_t ag = agbase + (size_t)(k0 + GBK);
            pah[0] = avalid ? *(const uint4*)(pAh + ag)     : zero4;
            pah[1] = avalid ? *(const uint4*)(pAh + ag + 8) : zero4;
            pal[0] = avalid ? *(const uint4*)(pAl + ag)     : zero4;
            pal[1] = avalid ? *(const uint4*)(pAl + ag + 8) : zero4;
            const size_t bg = bgbase + (size_t)((k0 + GBK) >> 1) * Nb;
            pbh[0] = *(const uint4*)((const __half2*)pBh + bg);
            pbh[1] = *(const uint4*)((const __half2*)pBh + bg + 4);
            pbl[0] = *(const uint4*)((const __half2*)pBl + bg);
            pbl[1] = *(const uint4*)((const __half2*)pBl + bg + 4);
        }

        // ---- mma on current buffer ----
        {
            const unsigned sA_hi = sbase + buf * STG_B;
            const unsigned sA_lo = sA_hi + AS_SZ * 4;
            const __half2* Bs_hi = dsm + buf * STG_H2 + 2 * AS_SZ;
            const __half2* Bs_lo = Bs_hi + BS_SZ;
#pragma unroll
            for (int ch = 0; ch < 2; ch++) {
                const int ko2 = ch * 8;
                unsigned bh[4][2], bl[4][2];
#pragma unroll
                for (int an = 0; an < 4; an++) {
                    int c0 = n_off + an * 8 + grp;
                    bh[an][0] = *(const unsigned*)&Bs_hi[(ko2 + tg) * B_LDH + c0];
                    bh[an][1] = *(const unsigned*)&Bs_hi[(ko2 + tg + 4) * B_LDH + c0];
                    bl[an][0] = *(const unsigned*)&Bs_lo[(ko2 + tg) * B_LDH + c0];
                    bl[an][1] = *(const unsigned*)&Bs_lo[(ko2 + tg + 4) * B_LDH + c0];
                }
#pragma unroll
                for (int am = 0; am < 4; am++) {
                    const int amoff = ((m_off + am * 16) * A_LDH + ko2) * 4 + lds_lane;
                    unsigned ah[4], al[4];
                    ldsm_x4(ah, sA_hi + amoff);
                    ldsm_x4(al, sA_lo + amoff);
#pragma unroll
                    for (int an = 0; an < 4; an++) {
                        mma_f16(cc[am][an], al, bh[an]);
                        mma_f16(cc[am][an], ah, bl[an]);
                        mma_f16(cc[am][an], ah, bh[an]);
                    }
                }
            }
        }

        // ---- store next tile into other buffer, single sync ----
        if (notlast) {
            __half2* As_hi = dsm + (buf ^ 1) * STG_H2;
            __half2* As_lo = As_hi + AS_SZ;
            __half2* Bs_hi = As_lo + AS_SZ;
            __half2* Bs_lo = Bs_hi + BS_SZ;
            *(uint4*)&As_hi[aoff] = pah[0]; *(uint4*)&As_hi[aoff + 4] = pah[1];
            *(uint4*)&As_lo[aoff] = pal[0]; *(uint4*)&As_lo[aoff + 4] = pal[1];
            *(uint4*)&Bs_hi[boff2] = pbh[0]; *(uint4*)&Bs_hi[boff2 + 4] = pbh[1];
            *(uint4*)&Bs_lo[boff2] = pbl[0]; *(uint4*)&Bs_lo[boff2 + 4] = pbl[1];
            __syncthreads();
        }
        buf ^= 1;
    }

    // ======================= epilogues =======================
    if (EPI == 0) {
        float* C = (float*)C0;
#pragma unroll
        for (int am = 0; am < 4; am++) {
            int r0 = bm + m_off + am * 16 + grp;
#pragma unroll
            for (int an = 0; an < 4; an++) {
                int c0 = bn * 2 + n_off * 2 + an * 16 + 4 * tg;  // fp32 col = 2*half2 col
                // NOTE: bn, n_off are in half2-column units for B; output col in halves
                ;
            }
        }
        // correct fp32 epilogue (cols in element units = 2 * half2 cols)
#pragma unroll
        for (int am = 0; am < 4; am++) {
            int r0 = bm + m_off + am * 16 + grp;
#pragma unroll
            for (int an = 0; an < 4; an++) {
                int c0 = 0;
                c0 = (bn + n_off + an * 8 + 2 * tg);  // placeholder; fixed below
                (void)c0;
            }
        }
        // --- real epilogue ---
#pragma unroll
        for (int am = 0; am < 4; am++) {
            int r0 = bm + m_off + am * 16 + grp;
#pragma unroll
            for (int an = 0; an < 4; an++) {
                int c0 = bn + n_off + an * 8 + 2 * tg;
                if (r0 < M)
                    *(float2*)&C[(size_t)r0 * 256 + c0] = make_float2(cc[am][an][0], cc[am][an][1]);
                if (r0 + 8 < M)
                    *(float2*)&C[(size_t)(r0 + 8) * 256 + c0] = make_float2(cc[am][an][2], cc[am][an][3]);
            }
        }
    } else if (EPI == 5 && bx < 2) {
        __half2* C = (__half2*)C0;
#pragma unroll
        for (int am = 0; am < 4; am++) {
            int r0 = bm + m_off + am * 16 + grp;
#pragma unroll
            for (int an = 0; an < 4; an++) {
                int c0 = bn + n_off + an * 8 + 2 * tg;
                if (r0 < M)
                    C[(size_t)r0 * 128 + (c0 >> 1)] = __floats2half2_rn(cc[am][an][0], cc[am][an][1]);
                if (r0 + 8 < M)
                    C[(size_t)(r0 + 8) * 128 + (c0 >> 1)] = __floats2half2_rn(cc[am][an][2], cc[am][an][3]);
            }
        }
    } else if (EPI == 5 && bx < 4) {
        int4* C = (int4*)C1;
#pragma unroll
        for (int am = 0; am < 4; am++) {
#pragma unroll
            for (int rh = 0; rh < 2; rh++) {
                int row = bm + m_off + am * 16 + grp + rh * 8;
                if (row >= M) continue;
#pragma unroll
                for (int an = 0; an < 4; an++) {
                    int c0 = bn + n_off + an * 8 + 2 * tg;   // even: x; c0+1: y
                    int l = (c0 >> 3) & 3;
                    const int Wl = 96 >> l;
                    const int start = 12288 - (12288 >> (2 * l));
                    const float scale = 0.5f * (float)(Wl - 1);
                    float rx = __ldg(&ref[(size_t)row * 8 + l * 2 + 0]);
                    float ry = __ldg(&ref[(size_t)row * 8 + l * 2 + 1]);
                    float o0 = tanhf(cc[am][an][rh * 2 + 0] + __ldg(&boff[c0]));
                    float o1 = tanhf(cc[am][an][rh * 2 + 1] + __ldg(&boff[c0 + 1]));
                    float lx = fminf(fmaxf(rx + o0, -1.f), 1.f);
                    float ly = fminf(fmaxf(ry + o1, -1.f), 1.f);
                    float x = (lx + 1.f) * scale;
                    float y = (ly + 1.f) * scale;
                    float x0f = floorf(x), y0f = floorf(y);
                    float wx = x - x0f, wy = y - y0f;
                    int x0 = min(max((int)x0f, 0), Wl - 1);
                    int x1 = min(x0 + 1, Wl - 1);
                    int y0 = min(max((int)y0f, 0), Wl - 1);
                    int y1 = min(y0 + 1, Wl - 1);
                    int base = (start + y0 * Wl + x0) * 128;
                    int dxdy = (((y1 - y0) * Wl * 128) << 8) | ((x1 - x0) * 128);
                    C[(size_t)row * 128 + (c0 >> 1)] =
                        make_int4(base, dxdy, __float_as_int(wx), __float_as_int(wy));
                }
            }
        }
    } else if (EPI == 5) {
        float* C = (float*)C2;
#pragma unroll
        for (int am = 0; am < 4; am++) {
#pragma unroll
            for (int rh = 0; rh < 2; rh++) {
                int row = bm + m_off + am * 16 + grp + rh * 8;
#pragma unroll
                for (int hd2 = 0; hd2 < 2; hd2++) {
                    float v[4];
#pragma unroll
                    for (int q = 0; q < 4; q++) {
                        int an = hd2 * 2 + (q >> 1);
                        int s = q & 1;
                        int col = n_off + an * 8 + 2 * tg + s;
                        v[q] = cc[am][an][rh * 2 + s] + __ldg(&battn[col]);
                    }
                    float m = fmaxf(fmaxf(v[0], v[1]), fmaxf(v[2], v[3]));
                    m = fmaxf(m, __shfl_xor_sync(0xffffffffu, m, 1));
                    m = fmaxf(m, __shfl_xor_sync(0xffffffffu, m, 2));
                    float e[4], sum = 0.f;
#pragma unroll
                    for (int q = 0; q < 4; q++) { e[q] = __expf(v[q] - m); sum += e[q]; }
                    sum += __shfl_xor_sync(0xffffffffu, sum, 1);
                    sum += __shfl_xor_sync(0xffffffffu, sum, 2);
                    float inv = 1.f / sum;
                    if (row < M) {
#pragma unroll
                        for (int a2 = 0; a2 < 2; a2++) {
                            int an = hd2 * 2 + a2;
                            int c0 = n_off + an * 8 + 2 * tg;
                            *(float2*)&C[(size_t)row * 128 + c0] =
                                make_float2(e[a2 * 2] * inv, e[a2 * 2 + 1] * inv);
                        }
                    }
                }
            }
        }
    }
}

// ---------------------------------------------------------------------------
// Deformable sampling: warp = one (bq, head-quad). 8 lanes per head, 4 channels
// per lane via 8B gathers. Epilogue splits acc into hi/lo fp16.
// ---------------------------------------------------------------------------
__device__ __forceinline__ float4 ld_corner(const __half2* p) {
    uint2 u = __ldg((const uint2*)p);
    float2 fa = __half22float2(*(__half2*)&u.x);
    float2 fb = __half22float2(*(__half2*)&u.y);
    return make_float4(fa.x, fa.y, fb.x, fb.y);
}

__global__ __launch_bounds__(256)
void sample_half(const __half2* __restrict__ vp,
                 const int4* __restrict__ sinfo,
                 const float* __restrict__ attnw,
                 __half* __restrict__ acch, __half* __restrict__ accl) {
    const int gwarp = (blockIdx.x * blockDim.x + threadIdx.x) >> 5;
    const int lane = threadIdx.x & 31;
    if (gwarp >= BQ_ * 2) return;
    const int wp = gwarp & 1;
    const int bq = gwarp >> 1;
    const int b = bq / Q_;
    const int hs = lane >> 3;
    const int c4 = lane & 7;
    const int h = wp * 4 + hs;

    const int4*  sp = sinfo + (size_t)bq * 128 + h * 16;
    const float* wq = attnw + (size_t)bq * 128 + h * 16;
    const __half2* vb = vp + (size_t)b * VLEN_ * 128 + h * 16 + c4 * 2;

    float a0 = 0.f, a1 = 0.f, a2 = 0.f, a3 = 0.f;
#pragma unroll
    for (int s = 0; s < 16; s++) {
        int4 si = __ldg(&sp[s]);
        float w = __ldg(&wq[s]);
        float wx = __int_as_float(si.z);
        float wy = __int_as_float(si.w);
        float wb = w * wy;
        float wa = w - wb;
        float w01 = wa * wx, w00 = wa - w01;
        float w11 = wb * wx, w10 = wb - w11;
        int dx = si.y & 255;
        int dy = si.y >> 8;
        const __half2* p = vb + si.x;
        float4 f00 = ld_corner(p);
        float4 f01 = ld_corner(p + dx);
        float4 f10 = ld_corner(p + dy);
        float4 f11 = ld_corner(p + dx + dy);
        a0 = fmaf(w00, f00.x, fmaf(w01, f01.x, fmaf(w10, f10.x, fmaf(w11, f11.x, a0))));
        a1 = fmaf(w00, f00.y, fmaf(w01, f01.y, fmaf(w10, f10.y, fmaf(w11, f11.y, a1))));
        a2 = fmaf(w00, f00.z, fmaf(w01, f01.z, fmaf(w10, f10.z, fmaf(w11, f11.z, a2))));
        a3 = fmaf(w00, f00.w, fmaf(w01, f01.w, fmaf(w10, f10.w, fmaf(w11, f11.w, a3))));
    }
    // split-store acc hi/lo
    float f[4] = {a0, a1, a2, a3};
    __half hs4[4], ls4[4];
#pragma unroll
    for (int j = 0; j < 4; j++) {
        hs4[j] = __float2half_rn(f[j]);
        ls4[j] = __float2half_rn(f[j] - __half2float(hs4[j]));
    }
    size_t off = (size_t)bq * 256 + h * 32 + c4 * 4;
    *(uint2*)(acch + off) = *(uint2*)hs4;
    *(uint2*)(accl + off) = *(uint2*)ls4;
}

// ---------------------------------------------------------------------------
extern "C" void kernel_launch(void* const* d_in, const int* in_sizes, int n_in,
                              void* d_out, int out_size) {
    const float* queries = (const float*)d_in[0];
    const float* ref     = (const float*)d_in[1];
    const float* value   = (const float*)d_in[2];
    const float* Wv      = (const float*)d_in[3];
    const float* Woff    = (const float*)d_in[4];
    const float* boff    = (const float*)d_in[5];
    const float* Wattn   = (const float*)d_in[6];
    const float* battn   = (const float*)d_in[7];
    const float* Wout    = (const float*)d_in[8];
    float* out = (float*)d_out;

    __half2* vproj;  int4* sinfo;  float* attnw;
    __half *valh, *vall, *qryh, *qryl, *acch, *accl;
    __half2 *wvh, *wvl, *woh, *wol, *wah, *wal, *wuh, *wul;
    cudaGetSymbolAddress((void**)&vproj, g_vproj_h);
    cudaGetSymbolAddress((void**)&sinfo, g_sinfo);
    cudaGetSymbolAddress((void**)&attnw, g_attnw);
    cudaGetSymbolAddress((void**)&valh, g_val_h);  cudaGetSymbolAddress((void**)&vall, g_val_l);
    cudaGetSymbolAddress((void**)&qryh, g_qry_h);  cudaGetSymbolAddress((void**)&qryl, g_qry_l);
    cudaGetSymbolAddress((void**)&acch, g_acc_h);  cudaGetSymbolAddress((void**)&accl, g_acc_l);
    cudaGetSymbolAddress((void**)&wvh, g_wv_h);    cudaGetSymbolAddress((void**)&wvl, g_wv_l);
    cudaGetSymbolAddress((void**)&woh, g_wo_h);    cudaGetSymbolAddress((void**)&wol, g_wo_l);
    cudaGetSymbolAddress((void**)&wah, g_wa_h);    cudaGetSymbolAddress((void**)&wal, g_wa_l);
    cudaGetSymbolAddress((void**)&wuh, g_wu_h);    cudaGetSymbolAddress((void**)&wul, g_wu_l);

    cudaFuncSetAttribute(gemm_3xfp16<5>, cudaFuncAttributeMaxDynamicSharedMemorySize, SMEM_TOT);
    cudaFuncSetAttribute(gemm_3xfp16<0>, cudaFuncAttributeMaxDynamicSharedMemorySize, SMEM_TOT);

    const int mblk = (BQ_ + GBM - 1) / GBM;   // 192

    // 0) prepasses
    split_inputs<<<dim3((unsigned)(NELEM / (256 * 8)), 2), 256>>>(value, queries, valh, vall, qryh, qryl);
    pack_weights<<<dim3(128, 4), 256>>>(Wv, Woff, Wattn, Wout,
                                        wvh, wvl, woh, wol, wah, wal, wuh, wul);
    // 1) merged front-end GEMMs
    gemm_3xfp16<5><<<dim3(5, mblk), 256, SMEM_TOT>>>(
        valh, vall, qryh, qryl, wvh, wvl, woh, wol, wah, wal,
        vproj, sinfo, attnw, BQ_, ref, boff, battn);
    // 2) deformable bilinear sampling -> acc hi/lo
    {
        int total_threads = BQ_ * 2 * 32;
        sample_half<<<(total_threads + 255) / 256, 256>>>(vproj, sinfo, attnw, acch, accl);
    }
    // 3) output projection -> d_out
    gemm_3xfp16<0><<<dim3(2, mblk), 256, SMEM_TOT>>>(
        acch, accl, nullptr, nullptr, wuh, wul, nullptr, nullptr, nullptr, nullptr,
        out, nullptr, nullptr, BQ_, nullptr, nullptr, nullptr);
}